// round 2
// baseline (speedup 1.0000x reference)
#include <cuda_runtime.h>

#define BB 64
#define NN 2048
#define CC 768
#define POOL 1024
#define PLEN 16
#define OUT_TOK (2*PLEN + NN)   /* 2080 */
#define EPSF 1e-12f
#define TOK_PER_BLK 128
#define NCHUNK (NN / TOK_PER_BLK)   /* 16 */

// Scratch (no allocations allowed in kernel_launch)
__device__ float g_xsum[BB*CC];
__device__ float g_pkrn[POOL];
__device__ float g_rpkrn[POOL];
__device__ int   g_idx[BB];
__device__ int   g_residx[BB];
__device__ float g_simsum[BB];

// ---------------------------------------------------------------------------
// K0: zero mean accumulators (graph replays must reset state)
// ---------------------------------------------------------------------------
__global__ void k0_zero() {
    int i = blockIdx.x * blockDim.x + threadIdx.x;
    if (i < BB*CC) g_xsum[i] = 0.0f;
}

// ---------------------------------------------------------------------------
// K_norm: rsqrt(max(||row||^2, eps)) for prompt_key (rows 0..1023) and
// residual_prompt_key (rows 1024..2047)
// ---------------------------------------------------------------------------
__global__ void k_norm(const float* __restrict__ pk, const float* __restrict__ rpk) {
    int row = blockIdx.x;
    const float* src = (row < POOL) ? (pk + (size_t)row*CC)
                                    : (rpk + (size_t)(row - POOL)*CC);
    float s = 0.f;
    for (int i = threadIdx.x; i < CC; i += 256) { float v = src[i]; s += v*v; }
    __shared__ float sh[8];
    int lane = threadIdx.x & 31, w = threadIdx.x >> 5;
    #pragma unroll
    for (int o = 16; o; o >>= 1) s += __shfl_xor_sync(0xffffffffu, s, o);
    if (lane == 0) sh[w] = s;
    __syncthreads();
    if (threadIdx.x == 0) {
        float t = 0.f;
        #pragma unroll
        for (int i = 0; i < 8; i++) t += sh[i];
        float r = rsqrtf(fmaxf(t, EPSF));
        if (row < POOL) g_pkrn[row] = r; else g_rpkrn[row - POOL] = r;
    }
}

// ---------------------------------------------------------------------------
// K1: stream x_embed into out[b, 32+n, :] AND accumulate per-(b,c) sums.
// 192 threads = 768/4 float4 columns; each block handles 128 tokens of one b.
// This is the HBM-bound kernel (~811 MB total traffic).
// ---------------------------------------------------------------------------
__global__ void __launch_bounds__(192)
k1_copy_reduce(const float* __restrict__ x, float* __restrict__ out) {
    int blk   = blockIdx.x;
    int b     = blk / NCHUNK;
    int chunk = blk % NCHUNK;
    int t     = threadIdx.x;   // 0..191 -> float4 column
    const float4* src = (const float4*)(x   + ((size_t)b*NN + (size_t)chunk*TOK_PER_BLK)*CC);
    float4*       dst = (float4*)(out + ((size_t)b*OUT_TOK + 2*PLEN + (size_t)chunk*TOK_PER_BLK)*CC);
    float4 s = make_float4(0.f, 0.f, 0.f, 0.f);
    #pragma unroll 4
    for (int n = 0; n < TOK_PER_BLK; n++) {
        float4 v = src[(size_t)n*(CC/4) + t];
        dst[(size_t)n*(CC/4) + t] = v;
        s.x += v.x; s.y += v.y; s.z += v.z; s.w += v.w;
    }
    float* acc = g_xsum + (size_t)b*CC + t*4;
    atomicAdd(acc + 0, s.x);
    atomicAdd(acc + 1, s.y);
    atomicAdd(acc + 2, s.z);
    atomicAdd(acc + 3, s.w);
}

// ---------------------------------------------------------------------------
// K2: per-batch-row selection. One block per b (256 threads).
//  1. x_norm = l2norm(mean)
//  2. argmax over sim = x_norm . pk[p] * rnorm[p]     (warp-cooperative dots)
//  3. residual = pk[idx] - x_norm
//  4. argmax over res_sim = residual . rpk[p] * rrnorm[p]
//  5. simsum[b] = max_sim + max_res_sim  (== pull-loss contributions)
// ---------------------------------------------------------------------------
__global__ void __launch_bounds__(256)
k2_select(const float* __restrict__ pk, const float* __restrict__ rpk) {
    __shared__ float s_vec[CC];
    __shared__ float s_wv[8];
    __shared__ int   s_wi[8];
    __shared__ float s_f;
    __shared__ int   s_i;

    int b    = blockIdx.x;
    int tid  = threadIdx.x;
    int lane = tid & 31, warp = tid >> 5;

    // ---- x_norm ----
    const float inv_n = 1.0f / (float)NN;
    float v0 = g_xsum[b*CC + tid      ] * inv_n;
    float v1 = g_xsum[b*CC + tid + 256] * inv_n;
    float v2 = g_xsum[b*CC + tid + 512] * inv_n;
    float ssq = v0*v0 + v1*v1 + v2*v2;
    #pragma unroll
    for (int o = 16; o; o >>= 1) ssq += __shfl_xor_sync(0xffffffffu, ssq, o);
    if (lane == 0) s_wv[warp] = ssq;
    __syncthreads();
    if (tid == 0) {
        float t = 0.f;
        #pragma unroll
        for (int i = 0; i < 8; i++) t += s_wv[i];
        s_f = rsqrtf(fmaxf(t, EPSF));
    }
    __syncthreads();
    float rn = s_f;
    s_vec[tid      ] = v0 * rn;
    s_vec[tid + 256] = v1 * rn;
    s_vec[tid + 512] = v2 * rn;
    __syncthreads();

    const float4* xv = (const float4*)s_vec;

    // ---- phase 1: sim vs prompt_key ----
    float best = -1e30f; int bidx = POOL;
    for (int p = warp; p < POOL; p += 8) {
        const float4* kr = (const float4*)(pk + (size_t)p*CC);
        float d = 0.f;
        #pragma unroll
        for (int i = 0; i < 6; i++) {
            float4 a  = kr[lane + 32*i];
            float4 xx = xv[lane + 32*i];
            d += a.x*xx.x + a.y*xx.y + a.z*xx.z + a.w*xx.w;
        }
        #pragma unroll
        for (int o = 16; o; o >>= 1) d += __shfl_xor_sync(0xffffffffu, d, o);
        d *= g_pkrn[p];
        if (d > best) { best = d; bidx = p; }  // p increases -> earliest kept on tie
    }
    if (lane == 0) { s_wv[warp] = best; s_wi[warp] = bidx; }
    __syncthreads();
    if (tid == 0) {
        float bv = -1e30f; int bi = POOL;
        for (int w = 0; w < 8; w++) {
            float wv = s_wv[w]; int wi = s_wi[w];
            if (wv > bv || (wv == bv && wi < bi)) { bv = wv; bi = wi; }
        }
        s_i = bi; s_f = bv;
    }
    __syncthreads();
    int   idx1   = s_i;
    float maxsim = s_f;
    __syncthreads();

    // ---- residual = prompt_key[idx1] - x_norm (overwrite s_vec) ----
    float r0 = pk[(size_t)idx1*CC + tid      ] - s_vec[tid      ];
    float r1 = pk[(size_t)idx1*CC + tid + 256] - s_vec[tid + 256];
    float r2 = pk[(size_t)idx1*CC + tid + 512] - s_vec[tid + 512];
    s_vec[tid      ] = r0;
    s_vec[tid + 256] = r1;
    s_vec[tid + 512] = r2;
    __syncthreads();

    // ---- phase 2: res_sim vs residual_prompt_key ----
    best = -1e30f; bidx = POOL;
    for (int p = warp; p < POOL; p += 8) {
        const float4* kr = (const float4*)(rpk + (size_t)p*CC);
        float d = 0.f;
        #pragma unroll
        for (int i = 0; i < 6; i++) {
            float4 a  = kr[lane + 32*i];
            float4 xx = xv[lane + 32*i];
            d += a.x*xx.x + a.y*xx.y + a.z*xx.z + a.w*xx.w;
        }
        #pragma unroll
        for (int o = 16; o; o >>= 1) d += __shfl_xor_sync(0xffffffffu, d, o);
        d *= g_rpkrn[p];
        if (d > best) { best = d; bidx = p; }
    }
    if (lane == 0) { s_wv[warp] = best; s_wi[warp] = bidx; }
    __syncthreads();
    if (tid == 0) {
        float bv = -1e30f; int bi = POOL;
        for (int w = 0; w < 8; w++) {
            float wv = s_wv[w]; int wi = s_wi[w];
            if (wv > bv || (wv == bv && wi < bi)) { bv = wv; bi = wi; }
        }
        g_idx[b]    = idx1;
        g_residx[b] = bi;
        g_simsum[b] = maxsim + bv;
    }
}

// ---------------------------------------------------------------------------
// K3: gather selected prompt rows into out[b, 0:32, :] + write pull-loss scalar
// ---------------------------------------------------------------------------
__global__ void __launch_bounds__(192)
k3_gather(const float* __restrict__ prompt, const float* __restrict__ rprompt,
          float* __restrict__ out, int out_size) {
    int j = blockIdx.x;
    if (j < BB * 2 * PLEN) {
        int b = j / (2*PLEN);
        int t = j % (2*PLEN);
        const float* src = (t < PLEN)
            ? (rprompt + ((size_t)g_residx[b]*PLEN + t)*CC)
            : (prompt  + ((size_t)g_idx[b]*PLEN + (t - PLEN))*CC);
        const float4* s4 = (const float4*)src;
        float4*       d4 = (float4*)(out + ((size_t)b*OUT_TOK + t)*CC);
        d4[threadIdx.x] = s4[threadIdx.x];
    } else if (threadIdx.x == 0) {
        // deterministic serial sum of 64 values, then scale by 1/B
        float s = 0.f;
        #pragma unroll
        for (int i = 0; i < BB; i++) s += g_simsum[i];
        size_t prompted = (size_t)BB * OUT_TOK * CC;
        if ((size_t)out_size > prompted)
            out[(size_t)out_size - 1] = s * (1.0f / (float)BB);
    }
}

// ---------------------------------------------------------------------------
extern "C" void kernel_launch(void* const* d_in, const int* in_sizes, int n_in,
                              void* d_out, int out_size) {
    const float* x       = (const float*)d_in[0];  // x_embed [64,2048,768]
    const float* prompt  = (const float*)d_in[1];  // [1024,16,768]
    const float* pk      = (const float*)d_in[2];  // [1024,768]
    const float* rprompt = (const float*)d_in[3];  // [1024,16,768]
    const float* rpk     = (const float*)d_in[4];  // [1024,768]
    float* out = (float*)d_out;

    k0_zero<<<(BB*CC + 255)/256, 256>>>();
    k_norm<<<2*POOL, 256>>>(pk, rpk);
    k1_copy_reduce<<<BB*NCHUNK, 192>>>(x, out);
    k2_select<<<BB, 256>>>(pk, rpk);
    k3_gather<<<BB*2*PLEN + 1, 192>>>(prompt, rprompt, out, out_size);
}